// round 2
// baseline (speedup 1.0000x reference)
#include <cuda_runtime.h>
#include <cuda_bf16.h>

// Problem constants (fixed by reference setup_inputs)
#define N_NODES 50000
#define CIN 64
#define COUT 64
#define E_MAX 800000

// -------- __device__ scratch (no allocations allowed) --------
__device__ float d_GW[N_NODES * COUT];    // G @ W^T            (12.8 MB)
__device__ float d_RWb[N_NODES * COUT];   // RSC @ W^T - b      (12.8 MB)
__device__ int   d_deg[N_NODES];          // per-dst degree
__device__ int   d_cursor[N_NODES];       // scan offsets / scatter cursors
__device__ int   d_esrc[E_MAX];           // src node id per edge, grouped by dst

// =====================================================================
// K0: zero the degree histogram
// =====================================================================
__global__ void k0_zero_deg() {
    int i = blockIdx.x * blockDim.x + threadIdx.x;
    if (i < N_NODES) d_deg[i] = 0;
}

// =====================================================================
// K1: fused GEMM: rows [0,N) -> GW = G @ W^T ; rows [N,2N) -> RWb = RSC @ W^T - b
// Block: 256 threads, 64-row x 64-col tile, 4x4 register tile per thread.
// Smem holds transposed G-tile and transposed W for conflict-free float4 LDS.
// =====================================================================
#define PAD 68   // 68 = 4*17 : keeps float4 alignment, breaks bank-conflict stride

__global__ __launch_bounds__(256) void k1_gemm(const float* __restrict__ G,
                                               const float* __restrict__ RSC,
                                               const float* __restrict__ W,
                                               const float* __restrict__ b) {
    __shared__ float Wt[64 * PAD];   // Wt[k][c] = W[c][k]
    __shared__ float Gt[64 * PAD];   // Gt[k][r] = in[row0+r][k]
    __shared__ float bs[64];

    const int tid  = threadIdx.x;
    const int row0 = blockIdx.x * 64;

    // Load W transposed (coalesced global read)
    #pragma unroll
    for (int idx = tid; idx < 64 * 64; idx += 256) {
        int c = idx >> 6, k = idx & 63;
        Wt[k * PAD + c] = W[idx];
    }
    if (tid < 64) bs[tid] = b[tid];

    // Load input tile transposed (coalesced global read)
    #pragma unroll
    for (int idx = tid; idx < 64 * 64; idx += 256) {
        int r = idx >> 6, k = idx & 63;
        int row = row0 + r;
        float v = 0.0f;
        if (row < N_NODES)           v = G[row * CIN + k];
        else if (row < 2 * N_NODES)  v = RSC[(row - N_NODES) * CIN + k];
        Gt[k * PAD + r] = v;
    }
    __syncthreads();

    const int tc = tid & 15;   // column group: cols 4*tc .. 4*tc+3
    const int tr = tid >> 4;   // row group:    rows 4*tr .. 4*tr+3

    float4 acc0 = {0.f,0.f,0.f,0.f};
    float4 acc1 = {0.f,0.f,0.f,0.f};
    float4 acc2 = {0.f,0.f,0.f,0.f};
    float4 acc3 = {0.f,0.f,0.f,0.f};

    #pragma unroll
    for (int k = 0; k < 64; k++) {
        float4 av = *reinterpret_cast<const float4*>(&Gt[k * PAD + 4 * tr]);
        float4 wv = *reinterpret_cast<const float4*>(&Wt[k * PAD + 4 * tc]);
        acc0.x += av.x * wv.x; acc0.y += av.x * wv.y; acc0.z += av.x * wv.z; acc0.w += av.x * wv.w;
        acc1.x += av.y * wv.x; acc1.y += av.y * wv.y; acc1.z += av.y * wv.z; acc1.w += av.y * wv.w;
        acc2.x += av.z * wv.x; acc2.y += av.z * wv.y; acc2.z += av.z * wv.z; acc2.w += av.z * wv.w;
        acc3.x += av.w * wv.x; acc3.y += av.w * wv.y; acc3.z += av.w * wv.z; acc3.w += av.w * wv.w;
    }

    float4 bb = *reinterpret_cast<const float4*>(&bs[4 * tc]);

    #pragma unroll
    for (int i = 0; i < 4; i++) {
        float4 o = (i == 0) ? acc0 : (i == 1) ? acc1 : (i == 2) ? acc2 : acc3;
        int row = row0 + 4 * tr + i;
        if (row < N_NODES) {
            *reinterpret_cast<float4*>(&d_GW[row * COUT + 4 * tc]) = o;
        } else if (row < 2 * N_NODES) {
            o.x -= bb.x; o.y -= bb.y; o.z -= bb.z; o.w -= bb.w;
            *reinterpret_cast<float4*>(&d_RWb[(row - N_NODES) * COUT + 4 * tc]) = o;
        }
    }
}

// =====================================================================
// K2: histogram of dst  (src/dst are int32: JAX x64 is disabled by default,
// so the reference's requested int64 silently downcasts to int32)
// =====================================================================
__global__ void k2_hist(const int* __restrict__ dst, int E) {
    int e = blockIdx.x * blockDim.x + threadIdx.x;
    if (e < E) {
        unsigned d = (unsigned)dst[e];
        if (d < N_NODES) atomicAdd(&d_deg[d], 1);   // clamp: crash insurance
    }
}

// =====================================================================
// K3: single-block exclusive scan of deg -> cursor (start offsets)
// =====================================================================
__global__ __launch_bounds__(1024) void k3_scan() {
    __shared__ int tsum[1024];
    const int CH = (N_NODES + 1023) / 1024;  // 49
    const int t = threadIdx.x;
    int beg = t * CH;
    int fin = beg + CH; if (fin > N_NODES) fin = N_NODES;

    int s = 0;
    for (int i = beg; i < fin; i++) s += d_deg[i];
    tsum[t] = s;
    __syncthreads();

    // Hillis-Steele inclusive scan with barriers
    for (int off = 1; off < 1024; off <<= 1) {
        int x = (t >= off) ? tsum[t - off] : 0;
        __syncthreads();
        tsum[t] += x;
        __syncthreads();
    }

    int run = tsum[t] - s;   // exclusive prefix
    for (int i = beg; i < fin; i++) {
        d_cursor[i] = run;
        run += d_deg[i];
    }
}

// =====================================================================
// K4: scatter edges into CSR buckets (stores int32 src id)
// =====================================================================
__global__ void k4_scatter(const int* __restrict__ src,
                           const int* __restrict__ dst, int E) {
    int e = blockIdx.x * blockDim.x + threadIdx.x;
    if (e < E) {
        unsigned d = (unsigned)dst[e];
        if (d < N_NODES) {
            int p = atomicAdd(&d_cursor[d], 1);
            unsigned s = (unsigned)src[e];
            d_esrc[p] = (s < N_NODES) ? (int)s : 0;
        }
    }
}

// =====================================================================
// K5: per-node aggregation. One warp per node; each lane owns 2 channels.
// enc = relu(GW[src] - RWb[node]) ; reduce max and mean over mailbox.
// Output: [N, 128] = concat(max[64], avg[64])
// =====================================================================
__global__ __launch_bounds__(256) void k5_agg(float* __restrict__ out) {
    const int warp = (blockIdx.x * blockDim.x + threadIdx.x) >> 5;
    if (warp >= N_NODES) return;
    const int lane = threadIdx.x & 31;
    const int node = warp;

    const int end = d_cursor[node];     // after scatter: start + deg
    const int deg = d_deg[node];
    const int start = end - deg;

    const float2 c = *reinterpret_cast<const float2*>(&d_RWb[node * COUT + 2 * lane]);

    float mx0 = 0.f, mx1 = 0.f, s0 = 0.f, s1 = 0.f;

    int i = start;
    // 4-way unroll: 4 independent gathers in flight (hide ~250cyc L2 latency)
    for (; i + 3 < end; i += 4) {
        int a = d_esrc[i], b_ = d_esrc[i+1], cidx = d_esrc[i+2], d = d_esrc[i+3];
        float2 g0 = *reinterpret_cast<const float2*>(&d_GW[a    * COUT + 2 * lane]);
        float2 g1 = *reinterpret_cast<const float2*>(&d_GW[b_   * COUT + 2 * lane]);
        float2 g2 = *reinterpret_cast<const float2*>(&d_GW[cidx * COUT + 2 * lane]);
        float2 g3 = *reinterpret_cast<const float2*>(&d_GW[d    * COUT + 2 * lane]);
        float v;
        v = fmaxf(g0.x - c.x, 0.f); mx0 = fmaxf(mx0, v); s0 += v;
        v = fmaxf(g0.y - c.y, 0.f); mx1 = fmaxf(mx1, v); s1 += v;
        v = fmaxf(g1.x - c.x, 0.f); mx0 = fmaxf(mx0, v); s0 += v;
        v = fmaxf(g1.y - c.y, 0.f); mx1 = fmaxf(mx1, v); s1 += v;
        v = fmaxf(g2.x - c.x, 0.f); mx0 = fmaxf(mx0, v); s0 += v;
        v = fmaxf(g2.y - c.y, 0.f); mx1 = fmaxf(mx1, v); s1 += v;
        v = fmaxf(g3.x - c.x, 0.f); mx0 = fmaxf(mx0, v); s0 += v;
        v = fmaxf(g3.y - c.y, 0.f); mx1 = fmaxf(mx1, v); s1 += v;
    }
    for (; i < end; i++) {
        int a = d_esrc[i];
        float2 g = *reinterpret_cast<const float2*>(&d_GW[a * COUT + 2 * lane]);
        float v;
        v = fmaxf(g.x - c.x, 0.f); mx0 = fmaxf(mx0, v); s0 += v;
        v = fmaxf(g.y - c.y, 0.f); mx1 = fmaxf(mx1, v); s1 += v;
    }

    const float inv = 1.0f / (float)((deg > 0) ? deg : 1);
    // max half
    out[node * 128 + 2 * lane]     = mx0;
    out[node * 128 + 2 * lane + 1] = mx1;
    // avg half
    out[node * 128 + 64 + 2 * lane]     = s0 * inv;
    out[node * 128 + 64 + 2 * lane + 1] = s1 * inv;
}

// =====================================================================
// launch
// =====================================================================
extern "C" void kernel_launch(void* const* d_in, const int* in_sizes, int n_in,
                              void* d_out, int out_size) {
    const float* G   = (const float*)d_in[0];
    const float* RSC = (const float*)d_in[1];
    const int*   src = (const int*)d_in[2];
    const int*   dst = (const int*)d_in[3];
    const float* W   = (const float*)d_in[4];
    const float* b   = (const float*)d_in[5];
    float* out = (float*)d_out;

    int E = in_sizes[2];
    if (E > E_MAX) E = E_MAX;

    // K0: zero histogram
    k0_zero_deg<<<(N_NODES + 255) / 256, 256>>>();

    // K1: GW / RWb (100000 rows, 64 per block)
    k1_gemm<<<(2 * N_NODES + 63) / 64, 256>>>(G, RSC, W, b);

    // K2: histogram
    k2_hist<<<(E + 255) / 256, 256>>>(dst, E);

    // K3: exclusive scan -> cursors
    k3_scan<<<1, 1024>>>();

    // K4: scatter into CSR
    k4_scatter<<<(E + 255) / 256, 256>>>(src, dst, E);

    // K5: per-node reduce (warp per node)
    k5_agg<<<(N_NODES * 32 + 255) / 256, 256>>>(out);
}

// round 3
// speedup vs baseline: 1.5161x; 1.5161x over previous
#include <cuda_runtime.h>
#include <cuda_bf16.h>

// Problem constants (fixed by reference setup_inputs)
#define N_NODES 50000
#define CIN 64
#define COUT 64
#define E_MAX 800000

// -------- __device__ scratch (no allocations allowed) --------
__device__ float d_GW[N_NODES * COUT];    // G @ W^T            (12.8 MB)
__device__ float d_RWb[N_NODES * COUT];   // RSC @ W^T - b      (12.8 MB)
__device__ int   d_deg[N_NODES];          // per-dst degree
__device__ int   d_cursor[N_NODES];       // scatter cursors (region start, then end)
__device__ int   d_esrc[E_MAX];           // src node id per edge, grouped by dst
__device__ int   d_alloc;                 // global region allocator

// =====================================================================
// K0: zero the degree histogram + allocator
// =====================================================================
__global__ void k0_zero_deg() {
    int i = blockIdx.x * blockDim.x + threadIdx.x;
    if (i < N_NODES) d_deg[i] = 0;
    if (i == 0) d_alloc = 0;
}

// =====================================================================
// K1: fused GEMM: rows [0,N) -> GW = G @ W^T ; rows [N,2N) -> RWb = RSC @ W^T - b
// Block: 256 threads, 64-row x 64-col tile, 4x4 register tile per thread.
// =====================================================================
#define PAD 68   // 68 = 4*17 : keeps float4 alignment, breaks bank-conflict stride

__global__ __launch_bounds__(256) void k1_gemm(const float* __restrict__ G,
                                               const float* __restrict__ RSC,
                                               const float* __restrict__ W,
                                               const float* __restrict__ b) {
    __shared__ float Wt[64 * PAD];   // Wt[k][c] = W[c][k]
    __shared__ float Gt[64 * PAD];   // Gt[k][r] = in[row0+r][k]
    __shared__ float bs[64];

    const int tid  = threadIdx.x;
    const int row0 = blockIdx.x * 64;

    #pragma unroll
    for (int idx = tid; idx < 64 * 64; idx += 256) {
        int c = idx >> 6, k = idx & 63;
        Wt[k * PAD + c] = W[idx];
    }
    if (tid < 64) bs[tid] = b[tid];

    #pragma unroll
    for (int idx = tid; idx < 64 * 64; idx += 256) {
        int r = idx >> 6, k = idx & 63;
        int row = row0 + r;
        float v = 0.0f;
        if (row < N_NODES)           v = G[row * CIN + k];
        else if (row < 2 * N_NODES)  v = RSC[(row - N_NODES) * CIN + k];
        Gt[k * PAD + r] = v;
    }
    __syncthreads();

    const int tc = tid & 15;
    const int tr = tid >> 4;

    float4 acc0 = {0.f,0.f,0.f,0.f};
    float4 acc1 = {0.f,0.f,0.f,0.f};
    float4 acc2 = {0.f,0.f,0.f,0.f};
    float4 acc3 = {0.f,0.f,0.f,0.f};

    #pragma unroll
    for (int k = 0; k < 64; k++) {
        float4 av = *reinterpret_cast<const float4*>(&Gt[k * PAD + 4 * tr]);
        float4 wv = *reinterpret_cast<const float4*>(&Wt[k * PAD + 4 * tc]);
        acc0.x += av.x * wv.x; acc0.y += av.x * wv.y; acc0.z += av.x * wv.z; acc0.w += av.x * wv.w;
        acc1.x += av.y * wv.x; acc1.y += av.y * wv.y; acc1.z += av.y * wv.z; acc1.w += av.y * wv.w;
        acc2.x += av.z * wv.x; acc2.y += av.z * wv.y; acc2.z += av.z * wv.z; acc2.w += av.z * wv.w;
        acc3.x += av.w * wv.x; acc3.y += av.w * wv.y; acc3.z += av.w * wv.z; acc3.w += av.w * wv.w;
    }

    float4 bb = *reinterpret_cast<const float4*>(&bs[4 * tc]);

    #pragma unroll
    for (int i = 0; i < 4; i++) {
        float4 o = (i == 0) ? acc0 : (i == 1) ? acc1 : (i == 2) ? acc2 : acc3;
        int row = row0 + 4 * tr + i;
        if (row < N_NODES) {
            *reinterpret_cast<float4*>(&d_GW[row * COUT + 4 * tc]) = o;
        } else if (row < 2 * N_NODES) {
            o.x -= bb.x; o.y -= bb.y; o.z -= bb.z; o.w -= bb.w;
            *reinterpret_cast<float4*>(&d_RWb[(row - N_NODES) * COUT + 4 * tc]) = o;
        }
    }
}

// =====================================================================
// K2: histogram of dst (int32 — JAX x64 disabled downcasts the int64 request)
// =====================================================================
__global__ void k2_hist(const int* __restrict__ dst, int E) {
    int e = blockIdx.x * blockDim.x + threadIdx.x;
    if (e < E) {
        unsigned d = (unsigned)dst[e];
        if (d < N_NODES) atomicAdd(&d_deg[d], 1);
    }
}

// =====================================================================
// K3: distributed region allocation. Each 1024-thread block scans its
// chunk of degrees (shfl warp scan + cross-warp scan), claims a base
// region via one atomicAdd on d_alloc, writes per-node start cursors.
// Region order across blocks is allocation-order; irrelevant to result.
// =====================================================================
__global__ __launch_bounds__(1024) void k3_scan() {
    const int t = threadIdx.x;
    const int i = blockIdx.x * 1024 + t;
    const int lane = t & 31;
    const int wid  = t >> 5;

    int v = (i < N_NODES) ? d_deg[i] : 0;

    // warp inclusive scan
    int x = v;
    #pragma unroll
    for (int o = 1; o < 32; o <<= 1) {
        int y = __shfl_up_sync(0xffffffffu, x, o);
        if (lane >= o) x += y;
    }

    __shared__ int wsum[32];
    __shared__ int base;
    if (lane == 31) wsum[wid] = x;
    __syncthreads();

    if (wid == 0) {
        int y = wsum[lane];
        #pragma unroll
        for (int o = 1; o < 32; o <<= 1) {
            int z = __shfl_up_sync(0xffffffffu, y, o);
            if (lane >= o) y += z;
        }
        wsum[lane] = y;                 // inclusive scan of warp sums
        if (lane == 31) base = atomicAdd(&d_alloc, y);  // y == block total
    }
    __syncthreads();

    int incl = x + ((wid > 0) ? wsum[wid - 1] : 0);
    if (i < N_NODES) d_cursor[i] = base + incl - v;   // exclusive start
}

// =====================================================================
// K4: scatter edges into CSR buckets (stores int32 src id)
// =====================================================================
__global__ void k4_scatter(const int* __restrict__ src,
                           const int* __restrict__ dst, int E) {
    int e = blockIdx.x * blockDim.x + threadIdx.x;
    if (e < E) {
        unsigned d = (unsigned)dst[e];
        if (d < N_NODES) {
            int p = atomicAdd(&d_cursor[d], 1);
            unsigned s = (unsigned)src[e];
            d_esrc[p] = (s < N_NODES) ? (int)s : 0;
        }
    }
}

// =====================================================================
// K5: per-node aggregation. One warp per node; each lane owns 2 channels.
// enc = relu(GW[src] - RWb[node]) ; reduce max and mean over mailbox.
// Output: [N, 128] = concat(max[64], avg[64])
// =====================================================================
__global__ __launch_bounds__(256) void k5_agg(float* __restrict__ out) {
    const int warp = (blockIdx.x * blockDim.x + threadIdx.x) >> 5;
    if (warp >= N_NODES) return;
    const int lane = threadIdx.x & 31;
    const int node = warp;

    const int end = d_cursor[node];     // after scatter: start + deg
    const int deg = d_deg[node];
    const int start = end - deg;

    const float2 c = *reinterpret_cast<const float2*>(&d_RWb[node * COUT + 2 * lane]);

    float mx0 = 0.f, mx1 = 0.f, s0 = 0.f, s1 = 0.f;

    int i = start;
    for (; i + 3 < end; i += 4) {
        int a = d_esrc[i], b_ = d_esrc[i+1], cidx = d_esrc[i+2], d = d_esrc[i+3];
        float2 g0 = *reinterpret_cast<const float2*>(&d_GW[a    * COUT + 2 * lane]);
        float2 g1 = *reinterpret_cast<const float2*>(&d_GW[b_   * COUT + 2 * lane]);
        float2 g2 = *reinterpret_cast<const float2*>(&d_GW[cidx * COUT + 2 * lane]);
        float2 g3 = *reinterpret_cast<const float2*>(&d_GW[d    * COUT + 2 * lane]);
        float v;
        v = fmaxf(g0.x - c.x, 0.f); mx0 = fmaxf(mx0, v); s0 += v;
        v = fmaxf(g0.y - c.y, 0.f); mx1 = fmaxf(mx1, v); s1 += v;
        v = fmaxf(g1.x - c.x, 0.f); mx0 = fmaxf(mx0, v); s0 += v;
        v = fmaxf(g1.y - c.y, 0.f); mx1 = fmaxf(mx1, v); s1 += v;
        v = fmaxf(g2.x - c.x, 0.f); mx0 = fmaxf(mx0, v); s0 += v;
        v = fmaxf(g2.y - c.y, 0.f); mx1 = fmaxf(mx1, v); s1 += v;
        v = fmaxf(g3.x - c.x, 0.f); mx0 = fmaxf(mx0, v); s0 += v;
        v = fmaxf(g3.y - c.y, 0.f); mx1 = fmaxf(mx1, v); s1 += v;
    }
    for (; i < end; i++) {
        int a = d_esrc[i];
        float2 g = *reinterpret_cast<const float2*>(&d_GW[a * COUT + 2 * lane]);
        float v;
        v = fmaxf(g.x - c.x, 0.f); mx0 = fmaxf(mx0, v); s0 += v;
        v = fmaxf(g.y - c.y, 0.f); mx1 = fmaxf(mx1, v); s1 += v;
    }

    const float inv = 1.0f / (float)((deg > 0) ? deg : 1);
    out[node * 128 + 2 * lane]          = mx0;
    out[node * 128 + 2 * lane + 1]      = mx1;
    out[node * 128 + 64 + 2 * lane]     = s0 * inv;
    out[node * 128 + 64 + 2 * lane + 1] = s1 * inv;
}

// =====================================================================
// launch
// =====================================================================
extern "C" void kernel_launch(void* const* d_in, const int* in_sizes, int n_in,
                              void* d_out, int out_size) {
    const float* G   = (const float*)d_in[0];
    const float* RSC = (const float*)d_in[1];
    const int*   src = (const int*)d_in[2];
    const int*   dst = (const int*)d_in[3];
    const float* W   = (const float*)d_in[4];
    const float* b   = (const float*)d_in[5];
    float* out = (float*)d_out;

    int E = in_sizes[2];
    if (E > E_MAX) E = E_MAX;

    k0_zero_deg<<<(N_NODES + 255) / 256, 256>>>();
    k1_gemm<<<(2 * N_NODES + 63) / 64, 256>>>(G, RSC, W, b);
    k2_hist<<<(E + 255) / 256, 256>>>(dst, E);
    k3_scan<<<(N_NODES + 1023) / 1024, 1024>>>();
    k4_scatter<<<(E + 255) / 256, 256>>>(src, dst, E);
    k5_agg<<<(N_NODES * 32 + 255) / 256, 256>>>(out);
}